// round 16
// baseline (speedup 1.0000x reference)
#include <cuda_runtime.h>
#include <math.h>
#include <stdint.h>

#define NB 2048
#define ND 1024
#define NH 2048
#define NO 512
#define NE 8
#define KSPLIT2 4

#define STAGES 6
#define A_STAGE_B (128 * 80)   // 128 rows * 20 words * 4B
#define B_STAGE_B (16 * 544)   // 16 k-rows * 136 words * 4B
#define SM_A 1024
#define SM_B (SM_A + STAGES * A_STAGE_B)
#define SMEM_TOTAL (SM_B + STAGES * B_STAGE_B)   // 114688 B -> 2 CTAs/SM

// ---------------- scratch ----------------
__device__ float g_H[(size_t)NE * 2048 * NH];                // expert hidden (slot-major)
__device__ float g_Lp[(size_t)KSPLIT2 * NE * 2048 * NO];     // split-K partial logits
__device__ int   g_count[NE];
__device__ int   g_rows[NE * 2048];
__device__ int   g_slot[NB * 2];
__device__ float g_gate[NB * 2];

#define PARTSZ ((size_t)NE * 2048 * NO)

// ---------------- helpers ----------------
__device__ __forceinline__ uint32_t smem_to_u32(const void* p) {
    uint32_t a;
    asm("{ .reg .u64 t; cvta.to.shared.u64 t, %1; cvt.u32.u64 %0, t; }" : "=r"(a) : "l"(p));
    return a;
}
__device__ __forceinline__ void cpa16(uint32_t dst, const void* src) {
    asm volatile("cp.async.cg.shared.global [%0], [%1], 16;" :: "r"(dst), "l"(src));
}
#define CP_COMMIT() asm volatile("cp.async.commit_group;" ::: "memory")
#define CP_WAIT(n)  asm volatile("cp.async.wait_group %0;" :: "n"(n) : "memory")
__device__ __forceinline__ uint32_t lds32(uint32_t a) {
    uint32_t v;
    asm volatile("ld.shared.b32 %0, [%1];" : "=r"(v) : "r"(a));
    return v;
}
__device__ __forceinline__ void ldsm4(uint32_t* r, uint32_t a) {
    asm volatile("ldmatrix.sync.aligned.m8n8.x4.shared.b16 {%0,%1,%2,%3}, [%4];"
        : "=r"(r[0]), "=r"(r[1]), "=r"(r[2]), "=r"(r[3]) : "r"(a));
}
__device__ __forceinline__ void mma8(float* c, const uint32_t* a, const uint32_t* b) {
    asm volatile(
        "mma.sync.aligned.m16n8k8.row.col.f32.tf32.tf32.f32 "
        "{%0,%1,%2,%3}, {%4,%5,%6,%7}, {%8,%9}, {%0,%1,%2,%3};"
        : "+f"(c[0]), "+f"(c[1]), "+f"(c[2]), "+f"(c[3])
        : "r"(a[0]), "r"(a[1]), "r"(a[2]), "r"(a[3]), "r"(b[0]), "r"(b[1]));
}

__global__ void zero_counts_kernel() {
    if (threadIdx.x < NE) g_count[threadIdx.x] = 0;
}

// One warp per token: logits, top-2 (first-index ties), softmax-of-2, scatter.
__global__ void gate_kernel(const float* __restrict__ x, const float* __restrict__ wg) {
    int warp = threadIdx.x >> 5, lane = threadIdx.x & 31;
    int b = blockIdx.x * 8 + warp;
    float acc[NE];
#pragma unroll
    for (int e = 0; e < NE; e++) acc[e] = 0.f;
    const float* xr = x + (size_t)b * ND;
    for (int d = lane; d < ND; d += 32) {
        float xv = xr[d];
#pragma unroll
        for (int e = 0; e < NE; e++) acc[e] += xv * wg[d * NE + e];
    }
#pragma unroll
    for (int e = 0; e < NE; e++)
#pragma unroll
        for (int off = 16; off; off >>= 1)
            acc[e] += __shfl_xor_sync(0xffffffffu, acc[e], off);
    if (lane == 0) {
        int i0 = 0; float l0 = acc[0];
#pragma unroll
        for (int e = 1; e < NE; e++) if (acc[e] > l0) { l0 = acc[e]; i0 = e; }
        int i1 = (i0 == 0) ? 1 : 0;
        float l1 = acc[i1];
#pragma unroll
        for (int e = 0; e < NE; e++)
            if (e != i0 && acc[e] > l1) { l1 = acc[e]; i1 = e; }
        float ex = expf(l1 - l0);
        float inv = 1.f / (1.f + ex);
        int p0 = atomicAdd(&g_count[i0], 1);
        g_rows[i0 * 2048 + p0] = b;
        g_slot[b * 2 + 0] = i0 * 2048 + p0;
        g_gate[b * 2 + 0] = inv;
        int p1 = atomicAdd(&g_count[i1], 1);
        g_rows[i1 * 2048 + p1] = b;
        g_slot[b * 2 + 1] = i1 * 2048 + p1;
        g_gate[b * 2 + 1] = ex * inv;
    }
}

// ---------------- TF32 grouped GEMM: CTA 128x128, 256 threads, 2 CTAs/SM, 6 stages of k16 ----------------
// 8 warps in 2x4 grid; warp tile 64x32. A via ldmatrix.x4.
// Two k-tiles per barrier; last ks-mma of each pair software-pipelined across the barrier.
// Group G_i = tiles {2i,2i+1}; committed end of iter i-2; wait_group(1) at iter top => G_i done.
template <int KCHUNK, int KFULL, int LDA, int LDB, int LDC, int KSPL, bool LUT, bool GELU>
__global__ __launch_bounds__(256, 2) void gemm_tf32(
    const float* __restrict__ Ain,   // x (LUT) / unused
    const float* __restrict__ Bin,   // w1 / w2 (expert-major)
    const float* __restrict__ bias)  // b1 (gemm2: unused)
{
    int e = blockIdx.z / KSPL;
    int ksp = blockIdx.z % KSPL;
    int cnt = g_count[e];
    int t0 = blockIdx.y * 128;
    if (t0 >= cnt) return;
    int n0 = blockIdx.x * 128;
    int kbase = ksp * KCHUNK;

    extern __shared__ char smem[];
    uint32_t sb = smem_to_u32(smem);
    int* rowsLUT = (int*)smem;
    int tid = threadIdx.x;
    int lane = tid & 31, wid = tid >> 5;
    int wm = wid >> 2, wn = wid & 3;

    if (LUT && tid < 128) rowsLUT[tid] = g_rows[e * 2048 + min(t0 + tid, cnt - 1)];
    __syncthreads();

    // cp.async setup: A = 2 x 16B per thread (rows r, r+64), B = 2 x 16B per thread
    const float* aptr[2];
    uint32_t adst[2];
#pragma unroll
    for (int i = 0; i < 2; i++) {
        int r = (tid >> 2) + 64 * i;
        const float* base;
        if (LUT) base = Ain + (size_t)rowsLUT[r] * LDA;
        else     base = (const float*)g_H + (size_t)(e * 2048 + t0 + r) * LDA;
        aptr[i] = base + kbase + (tid & 3) * 4;
        adst[i] = sb + SM_A + r * 80 + (tid & 3) * 16;
    }
    int kb = tid >> 5;
    const float* Bsrc = Bin + (size_t)e * KFULL * LDB + (size_t)kbase * LDB + n0 + (tid & 31) * 4;
    const float* bptr[2];
    uint32_t bdst[2];
#pragma unroll
    for (int j = 0; j < 2; j++) {
        bptr[j] = Bsrc + (size_t)(kb + 8 * j) * LDB;
        bdst[j] = sb + SM_B + (kb + 8 * j) * 544 + (tid & 31) * 16;
    }

    float c[4][4][4];
#pragma unroll
    for (int mt = 0; mt < 4; mt++)
#pragma unroll
        for (int nt = 0; nt < 4; nt++)
#pragma unroll
            for (int q = 0; q < 4; q++) c[mt][nt][q] = 0.f;

    // prologue: stages 0..3 = tiles 0..3; commit groups G0={t0,t1}, G1={t2,t3}
#pragma unroll
    for (int s = 0; s < 4; s++) {
        int k0 = s * 16;
#pragma unroll
        for (int i = 0; i < 2; i++) cpa16(adst[i] + s * A_STAGE_B, aptr[i] + k0);
#pragma unroll
        for (int j = 0; j < 2; j++) cpa16(bdst[j] + s * B_STAGE_B, bptr[j] + (size_t)k0 * LDB);
        if (s & 1) CP_COMMIT();
    }

    // ldmatrix lane base for A: matrices m0=rows g/k0-3, m1=g+8/k0-3, m2=g/k4-7, m3=g+8/k4-7
    int a_lm_row = wm * 64 + (lane & 7) + ((lane >> 3) & 1) * 8;
    uint32_t a_lm_base = sb + SM_A + a_lm_row * 80 + (lane >> 4) * 16;
    uint32_t b_frag_base = sb + SM_B + ((lane & 3) * 136 + wn * 32 + (lane >> 2)) * 4;

    const int NK = KCHUNK / 16;
    const int NKI = NK / 2;                 // tile pairs per CTA
    uint32_t af0[4][4], bf0[4][2], af1[4][4], bf1[4][2];

    // ---- macro-ish tile helpers (full tile, and tile-with-hoisted-ks1) ----
#define TILE_FULL(AB, BB)                                                      \
    do {                                                                       \
        _Pragma("unroll") for (int mt = 0; mt < 4; mt++) ldsm4(af0[mt], (AB) + mt * 1280); \
        _Pragma("unroll") for (int nt = 0; nt < 4; nt++) {                     \
            bf0[nt][0] = lds32((BB) + nt * 32);                                \
            bf0[nt][1] = lds32((BB) + 2176 + nt * 32);                         \
        }                                                                      \
        _Pragma("unroll") for (int mt = 0; mt < 4; mt++)                       \
            _Pragma("unroll") for (int nt = 0; nt < 4; nt++)                   \
                mma8(c[mt][nt], af0[mt], bf0[nt]);                             \
        _Pragma("unroll") for (int mt = 0; mt < 4; mt++) ldsm4(af0[mt], (AB) + mt * 1280 + 32); \
        _Pragma("unroll") for (int nt = 0; nt < 4; nt++) {                     \
            bf0[nt][0] = lds32((BB) + 4352 + nt * 32);                         \
            bf0[nt][1] = lds32((BB) + 4352 + 2176 + nt * 32);                  \
        }                                                                      \
        _Pragma("unroll") for (int mt = 0; mt < 4; mt++)                       \
            _Pragma("unroll") for (int nt = 0; nt < 4; nt++)                   \
                mma8(c[mt][nt], af0[mt], bf0[nt]);                             \
    } while (0)

#define TILE_HOIST(AB, BB)                                                     \
    do {                                                                       \
        _Pragma("unroll") for (int mt = 0; mt < 4; mt++) ldsm4(af0[mt], (AB) + mt * 1280); \
        _Pragma("unroll") for (int nt = 0; nt < 4; nt++) {                     \
            bf0[nt][0] = lds32((BB) + nt * 32);                                \
            bf0[nt][1] = lds32((BB) + 2176 + nt * 32);                         \
        }                                                                      \
        _Pragma("unroll") for (int mt = 0; mt < 4; mt++)                       \
            _Pragma("unroll") for (int nt = 0; nt < 4; nt++)                   \
                mma8(c[mt][nt], af0[mt], bf0[nt]);                             \
        _Pragma("unroll") for (int mt = 0; mt < 4; mt++) ldsm4(af1[mt], (AB) + mt * 1280 + 32); \
        _Pragma("unroll") for (int nt = 0; nt < 4; nt++) {                     \
            bf1[nt][0] = lds32((BB) + 4352 + nt * 32);                         \
            bf1[nt][1] = lds32((BB) + 4352 + 2176 + nt * 32);                  \
        }                                                                      \
    } while (0)

#define REFILL_PAIR(TR, SR)                                                    \
    do {                                                                       \
        if ((TR) < NK) {                                                       \
            _Pragma("unroll") for (int p = 0; p < 2; p++) {                    \
                int k0 = ((TR) + p) * 16;                                      \
                int so = (SR) + p;                                             \
                _Pragma("unroll") for (int i = 0; i < 2; i++)                  \
                    cpa16(adst[i] + so * A_STAGE_B, aptr[i] + k0);             \
                _Pragma("unroll") for (int j = 0; j < 2; j++)                  \
                    cpa16(bdst[j] + so * B_STAGE_B, bptr[j] + (size_t)k0 * LDB); \
            }                                                                  \
        }                                                                      \
        CP_COMMIT();                                                           \
    } while (0)

    // ---- peel pair 0 (tiles 0,1 in stages 0,1) ----
    CP_WAIT(1);
    __syncthreads();
    TILE_FULL(a_lm_base, b_frag_base);
    TILE_HOIST(a_lm_base + A_STAGE_B, b_frag_base + B_STAGE_B);
    REFILL_PAIR(4, 4);   // tiles 4,5 -> stages 4,5 (group G2)

    int sp = 0;   // stage of pair base, cycles 0 -> 2 -> 4 -> 0
    for (int i = 1; i < NKI; i++) {
        // hoisted ks1 of tile 2i-1 (register-only) covers the wait+barrier below
#pragma unroll
        for (int mt = 0; mt < 4; mt++)
#pragma unroll
            for (int nt = 0; nt < 4; nt++)
                mma8(c[mt][nt], af1[mt], bf1[nt]);

        CP_WAIT(1);          // G_i complete (newest pending = G_{i+1})
        __syncthreads();     // publish stages sp..sp+1
        sp += 2; if (sp == 6) sp = 0;
        uint32_t abA = a_lm_base + sp * A_STAGE_B;
        uint32_t bbA = b_frag_base + sp * B_STAGE_B;

        TILE_FULL(abA, bbA);
        TILE_HOIST(abA + A_STAGE_B, bbA + B_STAGE_B);

        // refill stages freed in iteration i-1 (tiles 2i+4, 2i+5); commit every iter
        int sr = sp + 4; if (sr >= 6) sr -= 6;
        REFILL_PAIR(2 * i + 4, sr);
    }

    // drain final hoisted ks1
#pragma unroll
    for (int mt = 0; mt < 4; mt++)
#pragma unroll
        for (int nt = 0; nt < 4; nt++)
            mma8(c[mt][nt], af1[mt], bf1[nt]);

#undef TILE_FULL
#undef TILE_HOIST
#undef REFILL_PAIR

    // epilogue
#pragma unroll
    for (int mt = 0; mt < 4; mt++) {
#pragma unroll
        for (int h = 0; h < 2; h++) {
            int lr = wm * 64 + mt * 16 + (lane >> 2) + h * 8;
            if (t0 + lr < cnt) {
                size_t rowoff = (size_t)(e * 2048 + t0 + lr) * LDC + n0 + wn * 32 + (lane & 3) * 2;
                if (GELU) {
                    const float* bias_e = bias + (size_t)e * LDC + n0 + wn * 32 + (lane & 3) * 2;
                    float* dst = g_H + rowoff;
#pragma unroll
                    for (int nt = 0; nt < 4; nt++) {
                        float2 bv = *(const float2*)(bias_e + nt * 8);
                        float v0 = c[mt][nt][h * 2 + 0] + bv.x;
                        float v1 = c[mt][nt][h * 2 + 1] + bv.y;
                        v0 = 0.5f * v0 * (1.0f + erff(v0 * 0.7071067811865476f));
                        v1 = 0.5f * v1 * (1.0f + erff(v1 * 0.7071067811865476f));
                        *(float2*)(dst + nt * 8) = make_float2(v0, v1);
                    }
                } else {
                    float* dst = g_Lp + (size_t)ksp * PARTSZ + rowoff;
#pragma unroll
                    for (int nt = 0; nt < 4; nt++)
                        *(float2*)(dst + nt * 8) =
                            make_float2(c[mt][nt][h * 2 + 0], c[mt][nt][h * 2 + 1]);
                }
            }
        }
    }
}

// Per-token: sum split-K partials + bias, logsumexp both expert rows, combine, log.
__global__ void combine_kernel(float* __restrict__ out, const float* __restrict__ b2) {
    int b = blockIdx.x;
    int tid = threadIdx.x;
    __shared__ float sred[256];
    int s0 = g_slot[b * 2], s1 = g_slot[b * 2 + 1];
    int e0 = s0 >> 11, e1 = s1 >> 11;
    float gg0 = g_gate[b * 2], gg1 = g_gate[b * 2 + 1];

    float v00, v01, v10, v11;
    {
        size_t r0 = (size_t)s0 * NO, r1 = (size_t)s1 * NO;
        v00 = b2[e0 * NO + tid]; v01 = b2[e0 * NO + tid + 256];
        v10 = b2[e1 * NO + tid]; v11 = b2[e1 * NO + tid + 256];
#pragma unroll
        for (int p = 0; p < KSPLIT2; p++) {
            const float* P = g_Lp + (size_t)p * PARTSZ;
            v00 += P[r0 + tid]; v01 += P[r0 + tid + 256];
            v10 += P[r1 + tid]; v11 += P[r1 + tid + 256];
        }
    }

    sred[tid] = fmaxf(v00, v01); __syncthreads();
    for (int s = 128; s; s >>= 1) { if (tid < s) sred[tid] = fmaxf(sred[tid], sred[tid + s]); __syncthreads(); }
    float m0 = sred[0]; __syncthreads();
    sred[tid] = expf(v00 - m0) + expf(v01 - m0); __syncthreads();
    for (int s = 128; s; s >>= 1) { if (tid < s) sred[tid] += sred[tid + s]; __syncthreads(); }
    float lse0 = m0 + logf(sred[0]); __syncthreads();

    sred[tid] = fmaxf(v10, v11); __syncthreads();
    for (int s = 128; s; s >>= 1) { if (tid < s) sred[tid] = fmaxf(sred[tid], sred[tid + s]); __syncthreads(); }
    float m1 = sred[0]; __syncthreads();
    sred[tid] = expf(v10 - m1) + expf(v11 - m1); __syncthreads();
    for (int s = 128; s; s >>= 1) { if (tid < s) sred[tid] += sred[tid + s]; __syncthreads(); }
    float lse1 = m1 + logf(sred[0]);

    out[(size_t)b * NO + tid]       = logf(gg0 * expf(v00 - lse0) + gg1 * expf(v10 - lse1));
    out[(size_t)b * NO + tid + 256] = logf(gg0 * expf(v01 - lse0) + gg1 * expf(v11 - lse1));
}

extern "C" void kernel_launch(void* const* d_in, const int* in_sizes, int n_in,
                              void* d_out, int out_size) {
    const float* x  = (const float*)d_in[0];
    const float* wg = (const float*)d_in[1];
    const float* w1 = (const float*)d_in[2];
    const float* b1 = (const float*)d_in[3];
    const float* w2 = (const float*)d_in[4];
    const float* b2 = (const float*)d_in[5];
    float* out = (float*)d_out;

    auto k1 = gemm_tf32<ND, ND, ND, NH, NH, 1, true, true>;
    auto k2 = gemm_tf32<NH / KSPLIT2, NH, NH, NO, NO, KSPLIT2, false, false>;
    cudaFuncSetAttribute((const void*)k1, cudaFuncAttributeMaxDynamicSharedMemorySize, SMEM_TOTAL);
    cudaFuncSetAttribute((const void*)k2, cudaFuncAttributeMaxDynamicSharedMemorySize, SMEM_TOTAL);

    zero_counts_kernel<<<1, 32>>>();
    gate_kernel<<<NB / 8, 256>>>(x, wg);
    k1<<<dim3(NH / 128, 16, NE), 256, SMEM_TOTAL>>>(x, w1, b1);
    k2<<<dim3(NO / 128, 16, NE * KSPLIT2), 256, SMEM_TOTAL>>>(x, w2, b2);
    combine_kernel<<<NB, 256>>>(out, b2);
}